// round 5
// baseline (speedup 1.0000x reference)
#include <cuda_runtime.h>
#include <math.h>
#include <stdint.h>

// StableMoEGate, SIMT fp32, packed fma.rn.f32x2 over K, occupancy-tuned.
// logits = x @ W^T (T=16384, H=4096, E=64); softmax; top-2; renorm softmax.
// Output: single f32 buffer [2T scores][2T idx-as-float][1 aux=0].
//
// CTA: 256 threads, 64 tokens x 64 experts. Warp grid 2 (tok) x 4 (exp);
// lanes 8 tok-lanes x 4 exp-lanes; thread micro-tile 4 tok x 4 exp (16 b64 acc).
// Double-buffered smem chunks of K=32: one __syncthreads per chunk.

#define Hdim 4096
#define Edim 64
#define MT   64
#define KT   32
#define NCH  (Hdim / KT)        // 128
#define BUFB 16384              // bytes per buffer (4096 floats: xs 2048 + ws 2048)

static __device__ __forceinline__ uint32_t smem_u32(const void* p) {
    uint32_t a;
    asm("{ .reg .u64 t; cvta.to.shared.u64 t, %1; cvt.u32.u64 %0, t; }" : "=r"(a) : "l"(p));
    return a;
}

__global__ __launch_bounds__(256, 2) void moe_gate_f32x2_v2_kernel(
    const float* __restrict__ x,
    const float* __restrict__ W,
    float* __restrict__ out,
    int T)
{
    __shared__ float smem[8192];          // 32 KB: two 16 KB buffers; epilogue overlays
    const uint32_t sbase = smem_u32(smem);

    const int tid = threadIdx.x;
    const int wid = tid >> 5;
    const int lid = tid & 31;
    const int m0  = blockIdx.x * MT;

    // compute mapping
    const int wr = wid >> 2;              // 0..1  token half
    const int wc = wid & 3;               // 0..3  expert quarter
    const int lt = lid & 7;               // 8 token lanes
    const int le = lid >> 3;              // 4 expert lanes
    // tok(i) = wr*32 + lt*4 + i ; e(j) = wc*16 + le*4 + j
    const int tokb = wr * 32 + lt * 4;
    const int eb   = wc * 16 + le * 4;
    const int wsw  = (wc * 4 + le) & 7;   // w swizzle key for this thread

    // loader mapping: rows lrow, lrow+32 ; 16B column lk
    const int lrow = tid >> 3;            // 0..31
    const int lk   = tid & 7;             // 0..7

    const float* xg = x + (size_t)(m0 + lrow) * Hdim + lk * 4;
    const float* wg = W + (size_t)lrow        * Hdim + lk * 4;
    const size_t rskip = (size_t)32 * Hdim;

    const int sc0 = lk ^ ((lrow >> 2) & 7);          // swizzled col, row lrow
    const int sc1 = lk ^ (((lrow + 32) >> 2) & 7);   // swizzled col, row lrow+32
    const uint32_t so_x0 = (uint32_t)(lrow * 128 + sc0 * 16);
    const uint32_t so_x1 = (uint32_t)((lrow + 32) * 128 + sc1 * 16);

    uint64_t acc[4][4];
    #pragma unroll
    for (int i = 0; i < 4; i++)
        #pragma unroll
        for (int j = 0; j < 4; j++) acc[i][j] = 0ull;

    // ---- preamble: load chunk 0, store to buf 0 ----
    {
        float4 ax0 = *(const float4*)(xg);
        float4 ax1 = *(const float4*)(xg + rskip);
        float4 aw0 = *(const float4*)(wg);
        float4 aw1 = *(const float4*)(wg + rskip);
        char* b0 = (char*)smem;
        *(float4*)(b0 + so_x0)        = ax0;
        *(float4*)(b0 + so_x1)        = ax1;
        *(float4*)(b0 + 8192 + so_x0) = aw0;
        *(float4*)(b0 + 8192 + so_x1) = aw1;
    }
    __syncthreads();

    for (int it = 0; it < NCH; it++) {
        // prefetch chunk it+1 (clamped; last-iter loads are redundant but harmless)
        const int kn = (it + 1 < NCH ? it + 1 : it) * KT;
        float4 nx0 = *(const float4*)(xg + kn);
        float4 nx1 = *(const float4*)(xg + kn + rskip);
        float4 nw0 = *(const float4*)(wg + kn);
        float4 nw1 = *(const float4*)(wg + kn + rskip);

        // compute on current buffer
        const uint32_t cb  = sbase + (uint32_t)((it & 1) * BUFB);
        const uint32_t cbw = cb + 8192;
        #pragma unroll
        for (int q = 0; q < 8; q++) {
            uint64_t xv0[4], xv1[4];
            const uint32_t xcol = (uint32_t)((q ^ lt) << 4);
            #pragma unroll
            for (int i = 0; i < 4; i++) {
                const uint32_t xa = cb + (uint32_t)((tokb + i) << 7) + xcol;
                asm volatile("ld.shared.v2.u64 {%0,%1},[%2];"
                             : "=l"(xv0[i]), "=l"(xv1[i]) : "r"(xa));
            }
            const uint32_t wcol = (uint32_t)((q ^ wsw) << 4);
            #pragma unroll
            for (int j = 0; j < 4; j++) {
                const uint32_t wa = cbw + (uint32_t)((eb + j) << 7) + wcol;
                uint64_t w0, w1;
                asm volatile("ld.shared.v2.u64 {%0,%1},[%2];"
                             : "=l"(w0), "=l"(w1) : "r"(wa));
                #pragma unroll
                for (int i = 0; i < 4; i++) {
                    asm("fma.rn.f32x2 %0, %1, %2, %0;" : "+l"(acc[i][j]) : "l"(xv0[i]), "l"(w0));
                    asm("fma.rn.f32x2 %0, %1, %2, %0;" : "+l"(acc[i][j]) : "l"(xv1[i]), "l"(w1));
                }
            }
        }

        // store prefetched chunk into the other buffer (safe: it was last read
        // before the previous barrier; wasted on final iteration)
        char* nb = (char*)smem + ((it + 1) & 1) * BUFB;
        *(float4*)(nb + so_x0)        = nx0;
        *(float4*)(nb + so_x1)        = nx1;
        *(float4*)(nb + 8192 + so_x0) = nw0;
        *(float4*)(nb + 8192 + so_x1) = nw1;
        __syncthreads();
    }

    // ---- epilogue: reduce pairs into logits smem [64][66] ----
    #pragma unroll
    for (int i = 0; i < 4; i++) {
        #pragma unroll
        for (int j = 0; j < 4; j++) {
            float lo, hi;
            asm("mov.b64 {%0,%1}, %2;" : "=f"(lo), "=f"(hi) : "l"(acc[i][j]));
            smem[(tokb + i) * 66 + (eb + j)] = lo + hi;
        }
    }
    __syncthreads();

    if (tid < MT) {
        const float* row = smem + tid * 66;
        float best1 = -3.4e38f, best2 = -3.4e38f;
        int i1 = 0, i2 = 0;
        #pragma unroll 8
        for (int e = 0; e < Edim; e++) {
            const float l = row[e];
            if (l > best1) { best2 = best1; i2 = i1; best1 = l; i1 = e; }
            else if (l > best2) { best2 = l; i2 = e; }
        }
        float Z = 0.0f;
        #pragma unroll 8
        for (int e = 0; e < Edim; e++) Z += expf(row[e] - best1);
        const float s1 = 1.0f / Z;
        const float s2 = expf(best2 - best1) / Z;
        const float p1 = 1.0f / (1.0f + expf(s2 - s1));
        const float p2 = 1.0f - p1;

        const int m = m0 + tid;
        out[2 * m + 0] = p1;
        out[2 * m + 1] = p2;
        float* oi = out + 2 * T;              // indices stored as float values
        oi[2 * m + 0] = (float)i1;
        oi[2 * m + 1] = (float)i2;
    }
    if (blockIdx.x == 0 && tid == 0) out[4 * T] = 0.0f;
}

extern "C" void kernel_launch(void* const* d_in, const int* in_sizes, int n_in,
                              void* d_out, int out_size)
{
    const float* x = (const float*)d_in[0];
    const float* W = (const float*)d_in[1];
    int T = in_sizes[0] / Hdim;   // 16384
    (void)n_in; (void)out_size;
    moe_gate_f32x2_v2_kernel<<<T / MT, 256>>>(x, W, (float*)d_out, T);
}

// round 6
// speedup vs baseline: 1.2792x; 1.2792x over previous
#include <cuda_runtime.h>
#include <math.h>
#include <stdint.h>

// StableMoEGate v3: FFMA2 GEMM, 8x8 micro-tile, in-CTA split-K(2), cp.async.
// logits = x @ W^T (T=16384, H=4096, E=64); softmax; top-2; renorm softmax.
// Output: single f32 buffer [2T scores][2T idx-as-float][1 aux=0].
//
// CTA: 128 thr (4 warps) = (K-group 0|1) x (expert half 0|1).
// Warp: 8 tok-lanes x 4 exp-lanes, 8x8 f32x2-accs per thread -> 64 tok x 32 exp.
// smem: 4 buffers (double-buffer x 2 K-groups) of [x 64x32k][w 64x32k] = 16KB each.

#define Hdim  4096
#define Edim  64
#define MT    64
#define KT    32
#define ITERS 64            // per K-group: 2048/32
#define BUFB  16384
#define SMEM_BYTES 65536

static __device__ __forceinline__ uint32_t smem_u32(const void* p) {
    uint32_t a;
    asm("{ .reg .u64 t; cvta.to.shared.u64 t, %1; cvt.u32.u64 %0, t; }" : "=r"(a) : "l"(p));
    return a;
}

__global__ void __launch_bounds__(128, 2) moe_gate_v3_kernel(
    const float* __restrict__ x,
    const float* __restrict__ W,
    float* __restrict__ out,
    int T)
{
    extern __shared__ float smem[];
    const uint32_t sbase = smem_u32(smem);

    const int tid = threadIdx.x;
    const int wid = tid >> 5;
    const int lid = tid & 31;
    const int m0  = blockIdx.x * MT;

    const int g    = wid >> 1;            // K-group: 0 -> k[0,2048), 1 -> k[2048,4096)
    const int we   = wid & 1;             // expert half
    const int lt   = lid & 7;             // token lane
    const int le   = lid >> 3;            // expert lane
    const int tokb = lt * 8;              // tokens tokb..tokb+7
    const int eb   = we * 32 + le * 8;    // experts eb..eb+7

    // ---- loader setup: 16 cp.async (16B) per thread per iteration ----
    const int lrow = tid >> 3;            // 0..15
    const int lcol = tid & 7;             // 0..7
    uint32_t xoff[4], woff[4];
    const char* xsrc[4];
    const char* wsrc[4];
    #pragma unroll
    for (int p = 0; p < 4; p++) {
        const int r = lrow + 16 * p;      // 0..63
        xoff[p] = (uint32_t)(r * 128 + ((lcol ^ ((r >> 3) & 7)) << 4));  // x key=(row>>3)&7
        woff[p] = (uint32_t)(r * 128 + ((lcol ^ (r & 7)) << 4));         // w key= row&7
        xsrc[p] = (const char*)(x + (size_t)(m0 + r) * Hdim + lcol * 4);
        wsrc[p] = (const char*)(W + (size_t)r * Hdim + lcol * 4);
    }

    auto issue = [&](int nt) {
        const uint32_t d = (uint32_t)(nt & 1);
        #pragma unroll
        for (int gg = 0; gg < 2; gg++) {
            const uint32_t bb = sbase + (d * 2 + gg) * BUFB;
            const int kb = (gg * 2048 + nt * KT) * 4;     // byte offset along K
            #pragma unroll
            for (int p = 0; p < 4; p++)
                asm volatile("cp.async.cg.shared.global [%0], [%1], 16;"
                             :: "r"(bb + xoff[p]), "l"(xsrc[p] + kb));
            #pragma unroll
            for (int p = 0; p < 4; p++)
                asm volatile("cp.async.cg.shared.global [%0], [%1], 16;"
                             :: "r"(bb + 8192 + woff[p]), "l"(wsrc[p] + kb));
        }
        asm volatile("cp.async.commit_group;" ::: "memory");
    };

    uint64_t acc[8][8];
    #pragma unroll
    for (int i = 0; i < 8; i++)
        #pragma unroll
        for (int j = 0; j < 8; j++) acc[i][j] = 0ull;

    issue(0);

    for (int it = 0; it < ITERS; it++) {
        asm volatile("cp.async.wait_group 0;" ::: "memory");
        __syncthreads();
        if (it + 1 < ITERS) issue(it + 1);

        const uint32_t base = sbase + (uint32_t)(((it & 1) * 2 + g) * BUFB);
        const uint32_t xb = base + (uint32_t)(tokb * 128);
        const uint32_t wb = base + 8192u + (uint32_t)(eb * 128);

        #pragma unroll
        for (int q = 0; q < 8; q++) {
            uint64_t xv0[8], xv1[8];
            const uint32_t xa = xb + (uint32_t)((q ^ lt) << 4);
            #pragma unroll
            for (int i = 0; i < 8; i++)
                asm volatile("ld.shared.v2.u64 {%0,%1},[%2];"
                             : "=l"(xv0[i]), "=l"(xv1[i]) : "r"(xa + (uint32_t)(i * 128)));
            #pragma unroll
            for (int j = 0; j < 8; j++) {
                // q, j compile-time constants -> (q^j)<<4 folds into the address
                const uint32_t wa = wb + (uint32_t)(j * 128 + ((q ^ j) << 4));
                uint64_t w0, w1;
                asm volatile("ld.shared.v2.u64 {%0,%1},[%2];"
                             : "=l"(w0), "=l"(w1) : "r"(wa));
                #pragma unroll
                for (int i = 0; i < 8; i++) {
                    asm("fma.rn.f32x2 %0, %1, %2, %0;" : "+l"(acc[i][j]) : "l"(xv0[i]), "l"(w0));
                    asm("fma.rn.f32x2 %0, %1, %2, %0;" : "+l"(acc[i][j]) : "l"(xv1[i]), "l"(w1));
                }
            }
        }
    }
    __syncthreads();

    // ---- combine K-groups in smem logits [64][66], then per-token scan ----
    if (g == 0) {
        #pragma unroll
        for (int i = 0; i < 8; i++)
            #pragma unroll
            for (int j = 0; j < 8; j++) {
                float lo, hi;
                asm("mov.b64 {%0,%1}, %2;" : "=f"(lo), "=f"(hi) : "l"(acc[i][j]));
                smem[(tokb + i) * 66 + (eb + j)] = lo + hi;
            }
    }
    __syncthreads();
    if (g == 1) {
        #pragma unroll
        for (int i = 0; i < 8; i++)
            #pragma unroll
            for (int j = 0; j < 8; j++) {
                float lo, hi;
                asm("mov.b64 {%0,%1}, %2;" : "=f"(lo), "=f"(hi) : "l"(acc[i][j]));
                smem[(tokb + i) * 66 + (eb + j)] += lo + hi;
            }
    }
    __syncthreads();

    if (tid < MT) {
        const float* row = smem + tid * 66;
        float best1 = -3.4e38f, best2 = -3.4e38f;
        int i1 = 0, i2 = 0;
        #pragma unroll 8
        for (int e = 0; e < Edim; e++) {
            const float l = row[e];
            if (l > best1) { best2 = best1; i2 = i1; best1 = l; i1 = e; }
            else if (l > best2) { best2 = l; i2 = e; }
        }
        float Z = 0.0f;
        #pragma unroll 8
        for (int e = 0; e < Edim; e++) Z += expf(row[e] - best1);
        const float s1 = 1.0f / Z;
        const float s2 = expf(best2 - best1) / Z;
        const float p1 = 1.0f / (1.0f + expf(s2 - s1));
        const float p2 = 1.0f - p1;

        const int m = m0 + tid;
        out[2 * m + 0] = p1;
        out[2 * m + 1] = p2;
        float* oi = out + 2 * T;              // indices stored as float values
        oi[2 * m + 0] = (float)i1;
        oi[2 * m + 1] = (float)i2;
    }
    if (blockIdx.x == 0 && tid == 0) out[4 * T] = 0.0f;
}

extern "C" void kernel_launch(void* const* d_in, const int* in_sizes, int n_in,
                              void* d_out, int out_size)
{
    const float* x = (const float*)d_in[0];
    const float* W = (const float*)d_in[1];
    int T = in_sizes[0] / Hdim;   // 16384
    (void)n_in; (void)out_size;

    static bool attr_done = false;
    if (!attr_done) {
        cudaFuncSetAttribute(moe_gate_v3_kernel,
                             cudaFuncAttributeMaxDynamicSharedMemorySize, SMEM_BYTES);
        attr_done = true;
    }
    moe_gate_v3_kernel<<<T / MT, 128, SMEM_BYTES>>>(x, W, (float*)d_out, T);
}